// round 4
// baseline (speedup 1.0000x reference)
#include <cuda_runtime.h>
#include <cooperative_groups.h>
#include <stdint.h>

namespace cg = cooperative_groups;

#define GH 52
#define GW 52
#define NB 5
#define NBOX 13520                 // 52*52*5
#define WORDS 423                  // ceil(NBOX/32)
#define CTAS 8
#define OWN 53                     // words per CTA (last CTA owns 52)
#define HALO 9                     // 9*32=288 bits >= 260+ gather reach
#define LW 72                      // HALO + OWN + HALO + 1 straddle word
#define NMS_T 512
#define IOU_T 0.4f

// Per-box predecessor masks: x=row dy=-1, y=row dy=0, z=row dy=+1 (15 bits
// each, bit (dx+1)*5+bb), w unused.
__device__ ushort4 g_pm[NBOX];

// ---------------------------------------------------------------------------
// Kernel 1: decode + per-row predecessor masks. One thread per (box, dy).
// Identical fp32 op sequence as the reference decode -> exact.
// ---------------------------------------------------------------------------
__global__ void decode_kernel(const float* __restrict__ x, float* __restrict__ out)
{
    int id = blockIdx.x * blockDim.x + threadIdx.x;
    if (id >= 3 * NBOX) return;
    int dyI = id / NBOX;           // 0,1,2 -> dy = dyI-1
    int j   = id - dyI * NBOX;

    int cell = j / NB;
    int b    = j - cell * NB;
    int gy   = cell / GW;
    int gx   = cell - gy * GW;

    const float sx = 416.0f / GW;  // 8
    const float sy = 416.0f / GH;  // 8

    const float* p = x + j * 5;
    float c0 = p[0], c1 = p[1], c2 = p[2], c3 = p[3], sj = p[4];

    float cx = (c0 + (float)gx) * sx;
    float w  = c2 * sx;
    float cy = (c1 + (float)gy) * sy;
    float h  = c3 * sy;
    cy = 416.0f - cy;
    float jx1 = cx - w * 0.5f, jy1 = cy - h * 0.5f;
    float jx2 = cx + w * 0.5f, jy2 = cy + h * 0.5f;

    if (dyI == 1) {
        float* o = out + j * 5;
        o[0] = jx1; o[1] = jy1; o[2] = jx2; o[3] = jy2;
        // o[4] written by nms_kernel.
    }

    float aj = fmaxf(jx2 - jx1, 0.0f) * fmaxf(jy2 - jy1, 0.0f);

    unsigned mask = 0;
    int ny = gy + dyI - 1;
    if ((unsigned)ny < GH) {
        #pragma unroll
        for (int dxi = 0; dxi < 3; dxi++) {
            int nx = gx + dxi - 1;
            if ((unsigned)nx >= GW) continue;
            int ncell = ny * GW + nx;
            #pragma unroll
            for (int bb = 0; bb < NB; bb++) {
                int i = ncell * NB + bb;
                if (i == j) continue;
                const float* q = x + i * 5;
                float si = q[4];
                bool higher = (si > sj) || (si == sj && i < j);
                if (!higher) continue;
                float d0 = q[0], d1 = q[1], d2 = q[2], d3 = q[3];
                float icx = (d0 + (float)nx) * sx;
                float iw_ = d2 * sx;
                float icy = (d1 + (float)ny) * sy;
                float ih_ = d3 * sy;
                icy = 416.0f - icy;
                float ix1 = icx - iw_ * 0.5f, iy1 = icy - ih_ * 0.5f;
                float ix2 = icx + iw_ * 0.5f, iy2 = icy + ih_ * 0.5f;

                float iw = fmaxf(fminf(ix2, jx2) - fmaxf(ix1, jx1), 0.0f);
                float ih = fmaxf(fminf(iy2, jy2) - fmaxf(iy1, jy1), 0.0f);
                float inter = iw * ih;
                float ai  = fmaxf(ix2 - ix1, 0.0f) * fmaxf(iy2 - iy1, 0.0f);
                float uni = ai + aj - inter;
                float iou = (uni > 0.0f) ? inter / fmaxf(uni, 1e-12f) : 0.0f;
                if (iou > IOU_T)
                    mask |= 1u << (dxi * 5 + bb);
            }
        }
    }
    ((unsigned short*)&g_pm[j])[dyI] = (unsigned short)mask;
}

// ---------------------------------------------------------------------------
// Kernel 2: clustered hierarchical fixpoint NMS. Per outer sweep: refresh
// halo (diff-tracked), iterate OWN words to local fixpoint with cheap block
// barriers + dirty-window frontier, then one cluster.sync. Terminate when
// every CTA's first inner iteration produced no change (certified fixpoint
// == exact greedy NMS).
// change map: bit (Lword + 7), 96 bits used, 3 rotating slots.
// ---------------------------------------------------------------------------
__device__ __forceinline__ uint32_t gather15(const uint32_t* L, int bit)
{
    int wi = bit >> 5;
    return __funnelshift_r(L[wi], L[wi + 1], bit) & 0x7FFFu;
}

__global__ void __cluster_dims__(CTAS, 1, 1)
nms_kernel(const float* __restrict__ x, float* __restrict__ out)
{
    __shared__ uint32_t L[LW];
    __shared__ uint32_t cmap[3][4];
    __shared__ int sCh[3];
    __shared__ int sAny;

    cg::cluster_group cl = cg::this_cluster();
    int r    = cl.block_rank();
    int t    = threadIdx.x;
    int lane = t & 31;
    int wid  = t >> 5;

    int w0     = r * OWN;
    int ownCnt = min(WORDS - w0, OWN);

    // Init kept: valid boxes = 1; last word keeps 16 bits; padding = 0.
    for (int i = t; i < LW; i += NMS_T) {
        int gw = w0 - HALO + i;
        uint32_t v = 0;
        if (gw >= 0 && gw < WORDS)
            v = (gw == WORDS - 1) ? 0x0000FFFFu : 0xFFFFFFFFu;
        L[i] = v;
    }
    if (t < 4) { cmap[0][t] = 0xFFFFFFFFu; cmap[1][t] = 0; cmap[2][t] = 0; }
    if (t < 3) sCh[t] = 0;
    if (t == 0) sAny = 1;

    uint32_t* Lprev = (r > 0)        ? (uint32_t*)cl.map_shared_rank(L, r - 1) : 0;
    uint32_t* Lnext = (r < CTAS - 1) ? (uint32_t*)cl.map_shared_rank(L, r + 1) : 0;
    int* chp = (t < CTAS) ? (int*)cl.map_shared_rank(sCh, t) : 0;

    // Static assignment: warp wid handles words wid + s*16.
    bool act[4]; bool val[4];
    int  lis[4]; int  lbs[4];
    uint32_t pA[4], pB[4], pC[4];
    #pragma unroll
    for (int s = 0; s < 4; s++) {
        int k = wid + s * 16;
        bool a = k < ownCnt;
        act[s] = a;
        int kk = a ? k : 0;
        int j  = (w0 + kk) * 32 + lane;
        bool v = a && (j < NBOX);
        val[s] = v;
        ushort4 pm = v ? g_pm[j] : make_ushort4(0, 0, 0, 0);
        pA[s] = pm.x; pB[s] = pm.y; pC[s] = pm.z;
        int b = j % 5;
        lis[s] = HALO + kk;
        lbs[s] = (HALO + kk) * 32 + lane - b - 5;
    }

    cl.sync();   // init visible cluster-wide

    int R = 0;       // read slot for first inner iteration of this sweep
    int fslot = 0;   // rotating cross-CTA flag slot
    for (int os = 0; os < NBOX; os++) {
        // --- halo refresh with diff tracking into cmap[R] ---
        if (t < HALO) {
            if (Lprev) {
                uint32_t nv = Lprev[t + OWN];
                if (nv != L[t]) {
                    L[t] = nv;
                    atomicOr(&cmap[R][(t + 7) >> 5], 1u << ((t + 7) & 31));
                }
            }
        } else if (t >= 32 && t < 32 + (LW - OWN - HALO)) {   // 10 words
            int li = OWN + HALO + (t - 32);
            if (Lnext) {
                uint32_t nv = Lnext[li - OWN];
                if (nv != L[li]) {
                    L[li] = nv;
                    atomicOr(&cmap[R][(li + 7) >> 5], 1u << ((li + 7) & 31));
                }
            }
        }
        // Reset flag slot for sweep os+1 (last read at sweep os-2: safe).
        if (t == NMS_T - 1) sCh[fslot == 2 ? 0 : fslot + 1] = 0;
        __syncthreads();

        // --- inner loop: local fixpoint with dirty-window frontier ---
        int ra = R;
        int dirty0 = 0;
        for (int it = 0; it < 256; it++) {
            int wa = (ra == 2) ? 0 : ra + 1;
            int za = (wa == 2) ? 0 : wa + 1;
            if (t < 4) cmap[za][t] = 0;       // next iter's write target

            int ch = 0;
            #pragma unroll
            for (int s = 0; s < 4; s++) {
                if (!act[s]) continue;
                int h  = lis[s];
                int bi = h - 2;
                uint64_t win = (uint64_t)cmap[ra][bi >> 5] |
                               ((uint64_t)cmap[ra][(bi >> 5) + 1] << 32);
                if (((win >> (bi & 31)) & 0xFFFFFu) == 0) continue;

                int lb = lbs[s];
                uint32_t rm1 = gather15(L, lb - 260);
                uint32_t r0  = gather15(L, lb);
                uint32_t rp1 = gather15(L, lb + 260);
                uint32_t sup = (rm1 & pA[s]) | (r0 & pB[s]) | (rp1 & pC[s]);
                bool keep = val[s] && (sup == 0u);
                uint32_t nw = __ballot_sync(0xFFFFFFFFu, keep);
                if (lane == 0 && L[h] != nw) {
                    L[h] = nw;
                    atomicOr(&cmap[wa][(h + 7) >> 5], 1u << ((h + 7) & 31));
                    ch = 1;
                }
            }
            int any = __syncthreads_or(ch);
            if (it == 0) dirty0 = any;
            ra = wa;
            if (!any) break;
        }
        R = ra;   // empty slot that next sweep's halo diffs flow into

        // --- cross-CTA convergence exchange ---
        if (t == 0 && dirty0) sCh[fslot] = 1;
        cl.sync();                                 // L + flags visible

        bool mine = (t < CTAS) ? (chp[fslot] != 0) : false;
        uint32_t bal = __ballot_sync(0xFFFFFFFFu, mine);
        if (t == 0) sAny = (int)(bal & 0xFFu);
        __syncthreads();
        if (!sAny) break;
        fslot = (fslot == 2) ? 0 : fslot + 1;
    }

    // Writeout: score if kept else 0, for own words.
    #pragma unroll
    for (int s = 0; s < 4; s++) {
        if (!act[s] || !val[s]) continue;
        int k = wid + s * 16;
        int j = (w0 + k) * 32 + lane;
        bool keep = (L[HALO + k] >> lane) & 1u;
        out[j * 5 + 4] = keep ? __ldg(&x[j * 5 + 4]) : 0.0f;
    }
}

// ---------------------------------------------------------------------------
extern "C" void kernel_launch(void* const* d_in, const int* in_sizes, int n_in,
                              void* d_out, int out_size)
{
    const float* x   = (const float*)d_in[0];
    float*       out = (float*)d_out;

    decode_kernel<<<(3 * NBOX + 255) / 256, 256>>>(x, out);
    nms_kernel<<<CTAS, NMS_T>>>(x, out);
}